// round 4
// baseline (speedup 1.0000x reference)
#include <cuda_runtime.h>

#define NN 768
#define NA 192
#define DD 128
#define HH 6
#define HD 768
#define NG 8
#define MM 96
#define PSZ (HD*NN)
#define SCALE 0.08838834764831845f
#define NB 144

// ---------------- device scratch ----------------
__device__ float g_p[3*PSZ];          // raw q,k,v projections (pre-LN)
__device__ float g_psum[3*NN*24];     // per (mat,row): 12 chunks x (sum, sumsq)
__device__ float g_att[NN*HD];        // attention output
__device__ float g_part[6*NN*DD];     // o1 split-K partials
__device__ int   g_inv[NN];           // node -> output row
__device__ unsigned int g_count = 0;
__device__ unsigned int g_gen = 0;

// grid-wide barrier: sense-free, generation-relative (safe across graph replays)
__device__ __forceinline__ void gsync(unsigned int base, unsigned int i) {
    __threadfence();
    __syncthreads();
    if (threadIdx.x == 0) {
        unsigned int old = atomicInc(&g_count, NB - 1u);
        if (old == NB - 1u) {
            atomicExch(&g_gen, base + i);
        } else {
            while ((*(volatile unsigned int*)&g_gen - base) < i) { }
            __threadfence();
        }
    }
    __syncthreads();
}

// dyn smem: sized for attn stage (the max)
#define DYN_SMEM ((4096 + 12544 + 224 + 224 + 384 + 384)*4 + 96*4)
#define KPITCH 130
#define VPITCH 98
#define SPITCH 98

__global__ void __launch_bounds__(256) megak(
    const float* __restrict__ agents, const int* __restrict__ agent_ids,
    const float* __restrict__ lanes,  const int* __restrict__ lane_ids,
    const float* __restrict__ Wq, const float* __restrict__ gq, const float* __restrict__ bq,
    const float* __restrict__ Wk, const float* __restrict__ gk, const float* __restrict__ bk,
    const float* __restrict__ Wv, const float* __restrict__ gv, const float* __restrict__ bv,
    const float* __restrict__ Wo1, const float* __restrict__ go1, const float* __restrict__ bo1,
    const float* __restrict__ Wo2, const float* __restrict__ W1,
    const float* __restrict__ gn, const float* __restrict__ bn,
    const float* __restrict__ W2, float* __restrict__ out)
{
    extern __shared__ float sm[];
    int tid = threadIdx.x;
    int bid = blockIdx.x;
    unsigned int base = 0;
    if (tid == 0) base = *(volatile unsigned int*)&g_gen;

    if (bid == 0) {
        for (int t = tid; t < NN; t += 256) {
            if (t < NA) g_inv[agent_ids[t]] = t;
            else        g_inv[NA + lane_ids[t - NA]] = t;
        }
    }

    // ================= stage 1: QKV GEMM (432 jobs of 64x64, K=128) ======
    {
        float* As = sm;                 // 64 x 130
        float* Bs = sm + 64*130;        // 64 x 130
        int tx = tid & 15, ty = tid >> 4;
        for (int r = 0; r < 3; r++) {
            int jid = bid + r*NB;
            int mt = jid % 12;
            int nt = jid / 12;          // 0..35
            int sel = nt / 12;
            int nch = nt % 12;
            int m0 = mt*64, w0 = nch*64;
            const float* W  = sel == 0 ? Wq : (sel == 1 ? Wk : Wv);
            const float* Ab = m0 < NA ? agents + m0*DD : lanes + (m0 - NA)*DD;
#pragma unroll
            for (int i = 0; i < 8; i++) {
                int lin = tid + i*256;
                int row = lin >> 5, c4 = lin & 31;
                float4 v = *(const float4*)&Ab[row*DD + c4*4];
                float* d = &As[row*130 + c4*4];
                d[0]=v.x; d[1]=v.y; d[2]=v.z; d[3]=v.w;
                float4 u = *(const float4*)&W[(w0+row)*DD + c4*4];
                float* e = &Bs[row*130 + c4*4];
                e[0]=u.x; e[1]=u.y; e[2]=u.z; e[3]=u.w;
            }
            __syncthreads();
            float acc[4][4] = {};
#pragma unroll 4
            for (int k2 = 0; k2 < DD; k2 += 2) {
                float2 a[4], b[4];
#pragma unroll
                for (int i = 0; i < 4; i++) a[i] = *(float2*)&As[(ty + 16*i)*130 + k2];
#pragma unroll
                for (int j = 0; j < 4; j++) b[j] = *(float2*)&Bs[(tx + 16*j)*130 + k2];
#pragma unroll
                for (int i = 0; i < 4; i++)
#pragma unroll
                    for (int j = 0; j < 4; j++) {
                        acc[i][j] += a[i].x * b[j].x;
                        acc[i][j] += a[i].y * b[j].y;
                    }
            }
            float* outp = g_p + sel*PSZ;
#pragma unroll
            for (int i = 0; i < 4; i++) {
#pragma unroll
                for (int j = 0; j < 4; j++)
                    outp[(m0 + ty + 16*i)*HD + w0 + tx + 16*j] = acc[i][j];
                float s = 0.f, s2 = 0.f;
#pragma unroll
                for (int j = 0; j < 4; j++) { s += acc[i][j]; s2 += acc[i][j]*acc[i][j]; }
#pragma unroll
                for (int o = 8; o > 0; o >>= 1) {
                    s  += __shfl_xor_sync(0xffffffffu, s,  o);
                    s2 += __shfl_xor_sync(0xffffffffu, s2, o);
                }
                if (tx == 0) {
                    int rr = m0 + ty + 16*i;
                    g_psum[(sel*NN + rr)*24 + nch*2 + 0] = s;
                    g_psum[(sel*NN + rr)*24 + nch*2 + 1] = s2;
                }
            }
            __syncthreads();
        }
    }
    gsync(base, 1);

    // ================= stage 2: fused attention (144 jobs, 1/block) ======
    {
        float* Qs  = sm;
        float* Ss  = sm;
        float* KV  = sm + 4096;
        float* s_mu = sm + 4096 + 12544;
        float* s_rs = s_mu + 224;
        float* s_g  = s_rs + 224;
        float* s_b  = s_g + 384;
        int*   mem  = (int*)(s_b + 384);

        int rb = bid % 3, head = (bid/3) % HH, gph = bid / (3*HH);
        if (tid < MM)
            mem[tid] = tid < 24 ? agent_ids[gph*24 + tid]
                                : NA + lane_ids[gph*72 + (tid - 24)];
        __syncthreads();
        if (tid < 224) {
            int mat, node;
            if (tid < 32)       { mat = 0; node = mem[rb*32 + tid]; }
            else if (tid < 128) { mat = 1; node = mem[tid - 32]; }
            else                { mat = 2; node = mem[tid - 128]; }
            const float* ps = &g_psum[(mat*NN + node)*24];
            float s = 0.f, s2 = 0.f;
#pragma unroll
            for (int n = 0; n < 12; n++) { s += ps[2*n]; s2 += ps[2*n+1]; }
            float mu = s * (1.f/HD);
            float var = s2 * (1.f/HD) - mu*mu;
            s_mu[tid] = mu;
            s_rs[tid] = rsqrtf(var + 1e-5f);
        }
        for (int t = tid; t < 384; t += 256) {
            int mat = t >> 7, c = t & 127;
            const float* g  = mat==0 ? gq : (mat==1 ? gk : gv);
            const float* bb = mat==0 ? bq : (mat==1 ? bk : bv);
            s_g[t] = g[head*DD + c];
            s_b[t] = bb[head*DD + c];
        }
        __syncthreads();
#pragma unroll
        for (int i = 0; i < 4; i++) {
            int lin = tid + i*256;
            int row = lin >> 5, c4 = lin & 31;
            int node = mem[rb*32 + row];
            float4 v = *(const float4*)&g_p[node*HD + head*DD + c4*4];
            float mu = s_mu[row], rs = s_rs[row];
            float* d = &Qs[row*128 + c4*4];
            d[0] = (v.x-mu)*rs*s_g[c4*4+0] + s_b[c4*4+0];
            d[1] = (v.y-mu)*rs*s_g[c4*4+1] + s_b[c4*4+1];
            d[2] = (v.z-mu)*rs*s_g[c4*4+2] + s_b[c4*4+2];
            d[3] = (v.w-mu)*rs*s_g[c4*4+3] + s_b[c4*4+3];
        }
#pragma unroll
        for (int i = 0; i < 12; i++) {
            int lin = tid + i*256;
            int row = lin >> 5, c4 = lin & 31;
            int node = mem[row];
            float4 v = *(const float4*)&g_p[PSZ + node*HD + head*DD + c4*4];
            float mu = s_mu[32+row], rs = s_rs[32+row];
            float* d = &KV[row*KPITCH + c4*4];
            d[0] = (v.x-mu)*rs*s_g[128+c4*4+0] + s_b[128+c4*4+0];
            d[1] = (v.y-mu)*rs*s_g[128+c4*4+1] + s_b[128+c4*4+1];
            d[2] = (v.z-mu)*rs*s_g[128+c4*4+2] + s_b[128+c4*4+2];
            d[3] = (v.w-mu)*rs*s_g[128+c4*4+3] + s_b[128+c4*4+3];
        }
        __syncthreads();

        int tx = tid & 15, ty = tid >> 4;
        float S[2][6] = {};
#pragma unroll 4
        for (int d2 = 0; d2 < DD; d2 += 2) {
            float2 a0 = *(float2*)&Qs[(2*ty+0)*128 + d2];
            float2 a1 = *(float2*)&Qs[(2*ty+1)*128 + d2];
#pragma unroll
            for (int j = 0; j < 6; j++) {
                float2 kk = *(float2*)&KV[(tx + 16*j)*KPITCH + d2];
                S[0][j] += a0.x*kk.x; S[0][j] += a0.y*kk.y;
                S[1][j] += a1.x*kk.x; S[1][j] += a1.y*kk.y;
            }
        }
        float p[2][6]; float inv[2];
#pragma unroll
        for (int i = 0; i < 2; i++) {
            float mx = S[i][0] * SCALE;
#pragma unroll
            for (int j = 1; j < 6; j++) mx = fmaxf(mx, S[i][j]*SCALE);
#pragma unroll
            for (int o = 8; o > 0; o >>= 1) mx = fmaxf(mx, __shfl_xor_sync(0xffffffffu, mx, o));
            float sum = 0.f;
#pragma unroll
            for (int j = 0; j < 6; j++) { p[i][j] = __expf(S[i][j]*SCALE - mx); sum += p[i][j]; }
#pragma unroll
            for (int o = 8; o > 0; o >>= 1) sum += __shfl_xor_sync(0xffffffffu, sum, o);
            inv[i] = 1.f / sum;
        }
        __syncthreads();
#pragma unroll
        for (int i = 0; i < 2; i++)
#pragma unroll
            for (int j = 0; j < 6; j++)
                Ss[(2*ty+i)*SPITCH + tx + 16*j] = p[i][j] * inv[i];
#pragma unroll
        for (int i = 0; i < 12; i++) {
            int lin = tid + i*256;
            int row = lin >> 5, c4 = lin & 31;
            int node = mem[row];
            float4 v = *(const float4*)&g_p[2*PSZ + node*HD + head*DD + c4*4];
            float mu = s_mu[128+row], rs = s_rs[128+row];
            KV[(c4*4+0)*VPITCH + row] = fmaxf((v.x-mu)*rs*s_g[256+c4*4+0] + s_b[256+c4*4+0], 0.f);
            KV[(c4*4+1)*VPITCH + row] = fmaxf((v.y-mu)*rs*s_g[256+c4*4+1] + s_b[256+c4*4+1], 0.f);
            KV[(c4*4+2)*VPITCH + row] = fmaxf((v.z-mu)*rs*s_g[256+c4*4+2] + s_b[256+c4*4+2], 0.f);
            KV[(c4*4+3)*VPITCH + row] = fmaxf((v.w-mu)*rs*s_g[256+c4*4+3] + s_b[256+c4*4+3], 0.f);
        }
        __syncthreads();
        float acc[2][8] = {};
#pragma unroll 4
        for (int k2 = 0; k2 < MM; k2 += 2) {
            float2 s0 = *(float2*)&Ss[(2*ty+0)*SPITCH + k2];
            float2 s1 = *(float2*)&Ss[(2*ty+1)*SPITCH + k2];
#pragma unroll
            for (int j = 0; j < 8; j++) {
                float2 vv = *(float2*)&KV[(tx + 16*j)*VPITCH + k2];
                acc[0][j] += s0.x*vv.x; acc[0][j] += s0.y*vv.y;
                acc[1][j] += s1.x*vv.x; acc[1][j] += s1.y*vv.y;
            }
        }
#pragma unroll
        for (int i = 0; i < 2; i++) {
            int node = mem[rb*32 + 2*ty + i];
#pragma unroll
            for (int j = 0; j < 8; j++)
                g_att[node*HD + head*DD + tx + 16*j] = acc[i][j];
        }
    }
    gsync(base, 2);

    // ================= stage 3: o1 split-K (24 row-tiles x 6 splits) =====
    {
        float* As = sm;             // 32 x 66
        float* Bs = sm + 32*66;     // 128 x 66
        int sp = bid / 24, mt = bid % 24;
        int m0 = mt*32, kb = sp*128;
        int tx = tid & 15, ty = tid >> 4;
        float acc[2][8] = {};
        for (int cc = 0; cc < 2; cc++) {
            int k0 = kb + cc*64;
#pragma unroll
            for (int i = 0; i < 2; i++) {
                int lin = tid + i*256;
                int row = lin >> 4, c4 = lin & 15;
                float4 v = *(const float4*)&g_att[(m0+row)*HD + k0 + c4*4];
                float* d = &As[row*66 + c4*4];
                d[0]=v.x; d[1]=v.y; d[2]=v.z; d[3]=v.w;
            }
#pragma unroll
            for (int i = 0; i < 8; i++) {
                int lin = tid + i*256;
                int row = lin >> 4, c4 = lin & 15;
                float4 v = *(const float4*)&Wo1[row*HD + k0 + c4*4];
                float* d = &Bs[row*66 + c4*4];
                d[0]=v.x; d[1]=v.y; d[2]=v.z; d[3]=v.w;
            }
            __syncthreads();
#pragma unroll 4
            for (int k2 = 0; k2 < 64; k2 += 2) {
                float2 a[2], b[8];
#pragma unroll
                for (int i = 0; i < 2; i++) a[i] = *(float2*)&As[(ty + 16*i)*66 + k2];
#pragma unroll
                for (int j = 0; j < 8; j++) b[j] = *(float2*)&Bs[(tx + 16*j)*66 + k2];
#pragma unroll
                for (int i = 0; i < 2; i++)
#pragma unroll
                    for (int j = 0; j < 8; j++) {
                        acc[i][j] += a[i].x * b[j].x;
                        acc[i][j] += a[i].y * b[j].y;
                    }
            }
            __syncthreads();
        }
#pragma unroll
        for (int i = 0; i < 2; i++)
#pragma unroll
            for (int j = 0; j < 8; j++)
                g_part[sp*(NN*DD) + (m0 + ty + 16*i)*DD + tx + 16*j] = acc[i][j];
    }
    gsync(base, 3);

    // ====== stage 4: reduce+LN -> mid GEMM+LN -> final GEMM+res+scatter ==
    if (bid < 96) {
        float* nodes_s = sm;                 // 8 x 130
        float* r1_s    = sm + 8*130;         // 8 x 130
        float* h_s     = sm + 2*8*130;       // 8 x 130
        float* Bs      = sm + 3*8*130;       // 128 x 34
        int m0 = bid*8;
        int row = tid >> 5, lane = tid & 31;
        const float* Ab = m0 < NA ? agents + m0*DD : lanes + (m0 - NA)*DD;
        {
            float4 v = *(const float4*)&Ab[row*DD + lane*4];
            float* d = &nodes_s[row*130 + lane*4];
            d[0]=v.x; d[1]=v.y; d[2]=v.z; d[3]=v.w;
        }
        // reduce o1 partials + LN(go1,bo1) + relu -> r1_s
        {
            float4 sv = make_float4(0.f,0.f,0.f,0.f);
#pragma unroll
            for (int sp = 0; sp < 6; sp++) {
                float4 v = *(const float4*)&g_part[sp*(NN*DD) + (m0+row)*DD + lane*4];
                sv.x += v.x; sv.y += v.y; sv.z += v.z; sv.w += v.w;
            }
            float s  = sv.x + sv.y + sv.z + sv.w;
            float s2 = sv.x*sv.x + sv.y*sv.y + sv.z*sv.z + sv.w*sv.w;
#pragma unroll
            for (int o = 16; o > 0; o >>= 1) {
                s  += __shfl_xor_sync(0xffffffffu, s,  o);
                s2 += __shfl_xor_sync(0xffffffffu, s2, o);
            }
            float mu = s*(1.f/DD), var = s2*(1.f/DD) - mu*mu;
            float rstd = rsqrtf(var + 1e-5f);
            float4 gg = *(const float4*)&go1[lane*4];
            float4 bb = *(const float4*)&bo1[lane*4];
            float* d = &r1_s[row*130 + lane*4];
            d[0] = fmaxf((sv.x-mu)*rstd*gg.x + bb.x, 0.f);
            d[1] = fmaxf((sv.y-mu)*rstd*gg.y + bb.y, 0.f);
            d[2] = fmaxf((sv.z-mu)*rstd*gg.z + bb.z, 0.f);
            d[3] = fmaxf((sv.w-mu)*rstd*gg.w + bb.w, 0.f);
        }
        __syncthreads();
        // mid GEMM: nodes@W1^T + r1@Wo2^T  (8x128, K=256)
        float acc[4] = {};
        for (int cc = 0; cc < 8; cc++) {
            const float* W = cc < 4 ? W1 : Wo2;
            const float* A = cc < 4 ? nodes_s : r1_s;
            int k0 = (cc & 3) * 32;
#pragma unroll
            for (int i = 0; i < 4; i++) {
                int lin = tid + i*256;
                int rw = lin >> 3, c4 = lin & 7;
                float4 v = *(const float4*)&W[rw*DD + k0 + c4*4];
                float* d = &Bs[rw*34 + c4*4];
                d[0]=v.x; d[1]=v.y; d[2]=v.z; d[3]=v.w;
            }
            __syncthreads();
#pragma unroll 4
            for (int k2 = 0; k2 < 32; k2 += 2) {
                float2 a = *(float2*)&A[row*130 + k0 + k2];
#pragma unroll
                for (int j = 0; j < 4; j++) {
                    float2 b = *(float2*)&Bs[(lane + 32*j)*34 + k2];
                    acc[j] += a.x*b.x; acc[j] += a.y*b.y;
                }
            }
            __syncthreads();
        }
        // LN(gn,bn) + relu -> h_s
        {
            float s = 0.f, s2 = 0.f;
#pragma unroll
            for (int j = 0; j < 4; j++) { s += acc[j]; s2 += acc[j]*acc[j]; }
#pragma unroll
            for (int o = 16; o > 0; o >>= 1) {
                s  += __shfl_xor_sync(0xffffffffu, s,  o);
                s2 += __shfl_xor_sync(0xffffffffu, s2, o);
            }
            float mu = s*(1.f/DD), var = s2*(1.f/DD) - mu*mu;
            float rstd = rsqrtf(var + 1e-5f);
#pragma unroll
            for (int j = 0; j < 4; j++) {
                int c = lane + 32*j;
                h_s[row*130 + c] = fmaxf((acc[j]-mu)*rstd*gn[c] + bn[c], 0.f);
            }
        }
        __syncthreads();
        // final GEMM: h @ W2^T (8x128, K=128) + residual + relu + scatter
        float acc2[4] = {};
        for (int cc = 0; cc < 4; cc++) {
            int k0 = cc * 32;
#pragma unroll
            for (int i = 0; i < 4; i++) {
                int lin = tid + i*256;
                int rw = lin >> 3, c4 = lin & 7;
                float4 v = *(const float4*)&W2[rw*DD + k0 + c4*4];
                float* d = &Bs[rw*34 + c4*4];
                d[0]=v.x; d[1]=v.y; d[2]=v.z; d[3]=v.w;
            }
            __syncthreads();
#pragma unroll 4
            for (int k2 = 0; k2 < 32; k2 += 2) {
                float2 a = *(float2*)&h_s[row*130 + k0 + k2];
#pragma unroll
                for (int j = 0; j < 4; j++) {
                    float2 b = *(float2*)&Bs[(lane + 32*j)*34 + k2];
                    acc2[j] += a.x*b.x; acc2[j] += a.y*b.y;
                }
            }
            __syncthreads();
        }
        int orow = g_inv[m0 + row];
#pragma unroll
        for (int j = 0; j < 4; j++) {
            int c = lane + 32*j;
            out[orow*DD + c] = fmaxf(acc2[j] + nodes_s[row*130 + c], 0.f);
        }
    }
}

// ------------------------------------------------------------------------
extern "C" void kernel_launch(void* const* d_in, const int* in_sizes, int n_in,
                              void* d_out, int out_size) {
    const float* agents    = (const float*)d_in[0];
    const int*   agent_ids = (const int*)  d_in[1];
    const float* lanes     = (const float*)d_in[2];
    const int*   lane_ids  = (const int*)  d_in[3];
    const float* Wq  = (const float*)d_in[4];
    const float* gq  = (const float*)d_in[5];
    const float* bq  = (const float*)d_in[6];
    const float* Wk  = (const float*)d_in[7];
    const float* gk  = (const float*)d_in[8];
    const float* bk  = (const float*)d_in[9];
    const float* Wv  = (const float*)d_in[10];
    const float* gv  = (const float*)d_in[11];
    const float* bv  = (const float*)d_in[12];
    const float* Wo1 = (const float*)d_in[13];
    const float* go1 = (const float*)d_in[14];
    const float* bo1 = (const float*)d_in[15];
    const float* Wo2 = (const float*)d_in[16];
    const float* W1  = (const float*)d_in[17];
    const float* gn  = (const float*)d_in[18];
    const float* bn  = (const float*)d_in[19];
    const float* W2  = (const float*)d_in[20];
    float* out = (float*)d_out;

    static int configured = 0;
    if (!configured) {
        cudaFuncSetAttribute(megak, cudaFuncAttributeMaxDynamicSharedMemorySize, DYN_SMEM);
        configured = 1;
    }

    megak<<<NB, 256, DYN_SMEM>>>(agents, agent_ids, lanes, lane_ids,
                                 Wq, gq, bq, Wk, gk, bk, Wv, gv, bv,
                                 Wo1, go1, bo1, Wo2, W1, gn, bn, W2, out);
}